// round 15
// baseline (speedup 1.0000x reference)
#include <cuda_runtime.h>
#include <cuda_fp16.h>

static constexpr int N_   = 20000;
static constexpr int E_   = 320000;
static constexpr int M_   = 3;
static constexpr int IN_  = 128;
static constexpr int H_   = 4;
static constexpr int D_   = 64;
static constexpr int HD_  = 256;   // H*D
static constexpr int HID_ = 128;

// ---------------- scratch (device globals; no runtime allocation) ----------------
// Invariant: g_deg, g_el, g_er, g_wsum are ZERO on entry and are re-zeroed by the
// pipeline after their last use (final / final / csr) so every replay is identical.
__device__ __half g_feat[(size_t)M_ * N_ * HD_];  // 30.7 MB fp16
__device__ __half g_z   [(size_t)M_ * N_ * HD_];  // 30.7 MB fp16
__device__ __half g_hh  [(size_t)N_ * IN_];       // 5.1 MB fp16 copy of h
__device__ float  g_el  [(size_t)M_ * N_ * H_];
__device__ float  g_er  [(size_t)M_ * N_ * H_];
__device__ float  g_ea  [(size_t)H_ * M_ * E_];   // alphas, HEAD-TRANSPOSED planes
__device__ int    g_deg [M_ * N_];
__device__ int    g_off [M_ * (N_ + 1)];          // RAW per-2048-block inclusive scan
__device__ int    g_rank[M_ * E_];                // edge rank within its dst (from hist)
__device__ int    g_srcs[M_ * E_];
__device__ int    g_bsum[M_ * 16];
__device__ float  g_wsum[M_];
__device__ int    g_cnt;                          // grid-barrier arrival counter
__device__ volatile int g_gen;                    // grid-barrier generation

__device__ __forceinline__ float lrelu(float x) { return x > 0.f ? x : 0.2f * x; }
__device__ __forceinline__ float fast_tanh(float x) {
    float y; asm("tanh.approx.f32 %0, %1;" : "=f"(y) : "f"(x)); return y;
}

// ---------------- tensor-core helpers ----------------
__device__ __forceinline__ void ldsm_x4(unsigned& r0, unsigned& r1, unsigned& r2, unsigned& r3,
                                        const void* p) {
    unsigned addr = (unsigned)__cvta_generic_to_shared(p);
    asm volatile("ldmatrix.sync.aligned.m8n8.x4.shared.b16 {%0,%1,%2,%3}, [%4];"
                 : "=r"(r0), "=r"(r1), "=r"(r2), "=r"(r3) : "r"(addr));
}
__device__ __forceinline__ void ldsm_x4_t(unsigned& r0, unsigned& r1, unsigned& r2, unsigned& r3,
                                          const void* p) {
    unsigned addr = (unsigned)__cvta_generic_to_shared(p);
    asm volatile("ldmatrix.sync.aligned.m8n8.x4.trans.shared.b16 {%0,%1,%2,%3}, [%4];"
                 : "=r"(r0), "=r"(r1), "=r"(r2), "=r"(r3) : "r"(addr));
}
__device__ __forceinline__ void mma16816(float* c, const unsigned* a, const unsigned* b) {
    asm volatile("mma.sync.aligned.m16n8k16.row.col.f32.f16.f16.f32 "
                 "{%0,%1,%2,%3}, {%4,%5,%6,%7}, {%8,%9}, {%0,%1,%2,%3};"
                 : "+f"(c[0]), "+f"(c[1]), "+f"(c[2]), "+f"(c[3])
                 : "r"(a[0]), "r"(a[1]), "r"(a[2]), "r"(a[3]), "r"(b[0]), "r"(b[1]));
}
__device__ __forceinline__ unsigned h2u(__half2 h) { return *reinterpret_cast<unsigned*>(&h); }
__device__ __forceinline__ uint4 pack8(float4 a, float4 b) {
    uint4 r;
    r.x = h2u(__floats2half2_rn(a.x, a.y));
    r.y = h2u(__floats2half2_rn(a.z, a.w));
    r.z = h2u(__floats2half2_rn(b.x, b.y));
    r.w = h2u(__floats2half2_rn(b.z, b.w));
    return r;
}

// ---------------- h fp32 -> fp16 (bit-identical to pack8 quantization) -----------
__global__ void convert_h_kernel(const float* __restrict__ h) {
    int i = blockIdx.x * blockDim.x + threadIdx.x;   // one float4 -> 4 halves
    constexpr int S = N_ * IN_ / 4;
    if (i >= S) return;
    float4 f = ((const float4*)h)[i];
    __half2 h0 = __floats2half2_rn(f.x, f.y);
    __half2 h1 = __floats2half2_rn(f.z, f.w);
    ((uint2*)g_hh)[i] = make_uint2(h2u(h0), h2u(h1));
}

// ---------------- tensor-core GEMM: BM=128,BN(64|128),BK=32, 8 warps -------------
// A from fp32 (A) or fp16 (Ah).  Epilogues:
//   Ch != nullptr : store fp16 C AND fused el/er partial dots (GEMM1)
//   W2 != nullptr : fused wsum[m] += sum tanh(acc+bias)*W2, no store (GEMM2)
// hdst != nullptr : 1-D launch; blocks beyond nbx*nby*M_ do the edge histogram
//                   AND record each edge's rank within its dst node.
template <int BN>
__global__ __launch_bounds__(256) void gemm_tc_kernel(
    const float* __restrict__ A, const __half* __restrict__ Ah,
    const float* __restrict__ B, __half* __restrict__ Ch,
    int Mrows, int K, int Ncols,
    long aStride, long bStride, long cStride,
    const float* __restrict__ bias, const float* __restrict__ W2,
    const float* __restrict__ attL, const float* __restrict__ attR,
    const int* __restrict__ hdst, int nbx, int nby)
{
    constexpr int BM = 128, BK = 32;
    constexpr int NT = BN / 16;        // 8-col mma tiles per warp (n)
    __shared__ __half As[BM][BK + 8];
    __shared__ __half Bs[BK][BN + 8];
    __shared__ float red[4];

    int bxi, byi, bzi;
    if (hdst) {
        int G = nbx * nby * M_;
        int b = blockIdx.x;
        if (b >= G) {               // histogram block: one edge per thread
            int i = (b - G) * 256 + threadIdx.x;
            if (i < M_ * E_)
                g_rank[i] = atomicAdd(&g_deg[(i / E_) * N_ + hdst[i]], 1);
            return;
        }
        bxi = b % nbx; byi = (b / nbx) % nby; bzi = b / (nbx * nby);
    } else {
        bxi = blockIdx.x; byi = blockIdx.y; bzi = blockIdx.z;
    }

    if (A) A += (long)bzi * aStride;
    B += (long)bzi * bStride;
    if (Ch) Ch += (long)bzi * cStride;

    int tid  = threadIdx.x;
    int lane = tid & 31, warp = tid >> 5;
    int wm = (warp & 3) * 32;
    int wn = (warp >> 2) * (BN / 2);
    int rowBase = bxi * BM, colBase = byi * BN;

    float acc[2][NT][4];
#pragma unroll
    for (int mt = 0; mt < 2; mt++)
#pragma unroll
        for (int nt = 0; nt < NT; nt++)
#pragma unroll
            for (int j = 0; j < 4; j++) acc[mt][nt][j] = 0.f;

    int arow = tid >> 1, acb = (tid & 1) * 16;
    int brow = tid >> 3, bcb = (tid & 7) * (BN / 8);
    bool aValid = (rowBase + arow) < Mrows;
    const float*  Abase  = A  ? A  + (long)(rowBase + arow) * K + acb : nullptr;
    const __half* Ahbase = Ah ? Ah + (long)(rowBase + arow) * K + acb : nullptr;
    const float*  Bbase  = B + (long)brow * Ncols + colBase + bcb;

    for (int k0 = 0; k0 < K; k0 += BK) {
        if (Ah) {
            uint4 q0 = make_uint4(0, 0, 0, 0), q1 = q0;
            if (aValid) {
                const __half* p = Ahbase + k0;
                q0 = *(const uint4*)p;
                q1 = *(const uint4*)(p + 8);
            }
            *(uint4*)&As[arow][acb]     = q0;
            *(uint4*)&As[arow][acb + 8] = q1;
        } else {
            float4 f0 = make_float4(0, 0, 0, 0), f1 = f0, f2 = f0, f3 = f0;
            if (aValid) {
                const float* p = Abase + k0;
                f0 = *(const float4*)(p + 0);  f1 = *(const float4*)(p + 4);
                f2 = *(const float4*)(p + 8);  f3 = *(const float4*)(p + 12);
            }
            *(uint4*)&As[arow][acb]     = pack8(f0, f1);
            *(uint4*)&As[arow][acb + 8] = pack8(f2, f3);
        }
        {
            const float* p = Bbase + (long)k0 * Ncols;
            float4 g0 = *(const float4*)(p + 0);
            float4 g1 = *(const float4*)(p + 4);
            *(uint4*)&Bs[brow][bcb] = pack8(g0, g1);
            if (BN == 128) {
                float4 g2 = *(const float4*)(p + 8);
                float4 g3 = *(const float4*)(p + 12);
                *(uint4*)&Bs[brow][bcb + 8] = pack8(g2, g3);
            }
        }
        __syncthreads();

#pragma unroll
        for (int kk = 0; kk < BK; kk += 16) {
            unsigned a[2][4], b[NT][2];
#pragma unroll
            for (int mt = 0; mt < 2; mt++)
                ldsm_x4(a[mt][0], a[mt][1], a[mt][2], a[mt][3],
                        &As[wm + mt * 16 + (lane & 15)][kk + (lane >> 4) * 8]);
#pragma unroll
            for (int np = 0; np < BN / 32; np++) {
                unsigned r0, r1, r2, r3;
                ldsm_x4_t(r0, r1, r2, r3,
                          &Bs[kk + (lane & 15)][wn + np * 16 + (lane >> 4) * 8]);
                b[2 * np][0] = r0; b[2 * np][1] = r1;
                b[2 * np + 1][0] = r2; b[2 * np + 1][1] = r3;
            }
#pragma unroll
            for (int mt = 0; mt < 2; mt++)
#pragma unroll
                for (int nt = 0; nt < NT; nt++)
                    mma16816(acc[mt][nt], a[mt], b[nt]);
        }
        __syncthreads();
    }

    bool fusedW2 = (W2 != nullptr);
    if (fusedW2) {
        if (tid < 4) red[tid] = 0.f;
        __syncthreads();
    }

    int gid = lane >> 2, tig = lane & 3;
    int head = (colBase + wn) >> 6;                // warp's 64-col slice = one head
    const float* al = attL ? attL + bzi * HD_ + colBase : nullptr;
    const float* ar = attL ? attR + bzi * HD_ + colBase : nullptr;

#pragma unroll
    for (int mt = 0; mt < 2; mt++) {
#pragma unroll
        for (int half = 0; half < 2; half++) {
            int row = rowBase + wm + mt * 16 + gid + half * 8;
            bool rv = row < Mrows;
            if (fusedW2) {
                if (rv) {
                    int m = row / N_;
                    float s = 0.f;
#pragma unroll
                    for (int nt = 0; nt < NT; nt++) {
                        int col = colBase + wn + nt * 8 + tig * 2;
                        s += fast_tanh(acc[mt][nt][2 * half] + bias[col]) * W2[col];
                        s += fast_tanh(acc[mt][nt][2 * half + 1] + bias[col + 1]) * W2[col + 1];
                    }
                    atomicAdd(&red[m], s);
                }
            } else {
                if (rv) {
                    __half* cp = Ch + (long)row * Ncols + colBase + wn + tig * 2;
#pragma unroll
                    for (int nt = 0; nt < NT; nt++) {
                        __half2 v = __floats2half2_rn(acc[mt][nt][2 * half],
                                                      acc[mt][nt][2 * half + 1]);
                        *(__half2*)(cp + nt * 8) = v;
                    }
                }
                if (al) {
                    float sel = 0.f, ser = 0.f;
#pragma unroll
                    for (int nt = 0; nt < NT; nt++) {
                        int cl = wn + nt * 8 + tig * 2;
                        float v0 = acc[mt][nt][2 * half], v1 = acc[mt][nt][2 * half + 1];
                        sel += v0 * al[cl] + v1 * al[cl + 1];
                        ser += v0 * ar[cl] + v1 * ar[cl + 1];
                    }
                    sel += __shfl_xor_sync(0xffffffffu, sel, 1);
                    sel += __shfl_xor_sync(0xffffffffu, sel, 2);
                    ser += __shfl_xor_sync(0xffffffffu, ser, 1);
                    ser += __shfl_xor_sync(0xffffffffu, ser, 2);
                    if (rv && tig == 0) {
                        size_t idx = ((size_t)bzi * N_ + row) * 4 + head;
                        atomicAdd(&g_el[idx], sel);
                        atomicAdd(&g_er[idx], ser);
                    }
                }
            }
        }
    }
    if (fusedW2) {
        __syncthreads();
        if (tid < 3) atomicAdd(&g_wsum[tid], red[tid]);
    }
}

// ---------------- CSR: scan (30 blocks) + grid barrier + scatter (all blocks) -----
// 296 blocks x 256 threads = exactly 2 blocks/SM -> all co-resident, so the
// software grid barrier (generation counter) cannot deadlock.
static constexpr int CSR_BLOCKS = 296;

__global__ __launch_bounds__(256) void csr_kernel(const int* __restrict__ src,
                                                  const int* __restrict__ dst) {
    int tid = threadIdx.x;

    // ---- phase 0: per-2048-node block scans (first 30 blocks only) ----
    if (blockIdx.x < 10 * M_) {
        int m = blockIdx.x / 10, b = blockIdx.x % 10;
        if (blockIdx.x == 0 && tid == 0) {          // pre-GEMM2 zero
            g_wsum[0] = 0.f; g_wsum[1] = 0.f; g_wsum[2] = 0.f;
        }
        int i0 = b * 2048 + tid * 8;
        int v[8];
        int s = 0;
#pragma unroll
        for (int j = 0; j < 8; j++) {
            int i = i0 + j;
            int d = (i < N_) ? g_deg[m * N_ + i] : 0;
            s += d; v[j] = s;
        }
        __shared__ int sh[256];
        sh[tid] = s;
        __syncthreads();
#pragma unroll
        for (int st = 1; st < 256; st <<= 1) {
            int y = (tid >= st) ? sh[tid - st] : 0;
            __syncthreads();
            sh[tid] += y;
            __syncthreads();
        }
        int excl = sh[tid] - s;
#pragma unroll
        for (int j = 0; j < 8; j++) {
            int i = i0 + j;
            if (i < N_) g_off[m * (N_ + 1) + i + 1] = excl + v[j];
        }
        if (tid == 255) g_bsum[m * 16 + b] = sh[255];
    }

    // ---- grid barrier (release scan writes, acquire before scatter reads) ----
    __threadfence();
    __syncthreads();
    if (tid == 0) {
        int target = g_gen + 1;      // pre-arrival read: gen can't advance yet
        int old = atomicAdd(&g_cnt, 1);
        if (old == CSR_BLOCKS - 1) {
            g_cnt = 0;
            __threadfence();
            g_gen = target;
        } else {
            while (g_gen < target) { }
        }
    }
    __syncthreads();
    __threadfence();

    // ---- smem block-prefix table ----
    __shared__ int sboff[M_ * 16];
    if (tid < M_ * 16) {
        int m = tid >> 4, b = tid & 15;
        int s = 0;
        for (int k = 0; k < b; k++) s += g_bsum[m * 16 + k];
        sboff[tid] = s;
    }
    __syncthreads();

    // ---- phase 1: scatter, grid-stride, 4 independent edges per thread ----
    for (int t0 = blockIdx.x * 1024; t0 < M_ * E_; t0 += CSR_BLOCKS * 1024) {
        int idx[4], dd[4], rk[4], sr[4], mm[4];
        bool val[4];
#pragma unroll
        for (int j = 0; j < 4; j++) {
            int i = t0 + tid + j * 256;
            idx[j] = i;
            val[j] = i < M_ * E_;
            if (val[j]) {
                dd[j] = dst[i];
                rk[j] = g_rank[i];
                sr[j] = src[i];
                mm[j] = i / E_;
            }
        }
        int off[4];
#pragma unroll
        for (int j = 0; j < 4; j++)
            if (val[j] && dd[j] != 0)
                off[j] = g_off[mm[j] * (N_ + 1) + dd[j]];
#pragma unroll
        for (int j = 0; j < 4; j++) {
            if (!val[j]) continue;
            int pos;
            if (dd[j] == 0) {
                pos = rk[j];
            } else {
                int blk = (dd[j] - 1) >> 11;
                pos = off[j] + sboff[mm[j] * 16 + blk] + rk[j];
            }
            g_srcs[mm[j] * E_ + pos] = sr[j];
        }
    }
}

// ---------------- GAT aggregate: one warp per (metapath, dst) -------------------
// pass A: exp once per (edge,head) -> 4 head-transposed alpha planes + denominators
// pass B: serial edges, unroll x4, scalar UNNORMALIZED alpha loads; normalize at end
__device__ __forceinline__ void addmul8(float* acc, float a, uint4 u) {
    const __half2* hp = (const __half2*)&u;
#pragma unroll
    for (int j = 0; j < 4; j++) {
        float2 x = __half22float2(hp[j]);
        acc[2 * j]     += a * x.x;
        acc[2 * j + 1] += a * x.y;
    }
}

__global__ __launch_bounds__(256) void agg_kernel(const float* __restrict__ bias) {
    int g = blockIdx.x * blockDim.x + threadIdx.x;
    int warp = g >> 5, lane = g & 31;
    if (warp >= M_ * N_) return;
    int m = warp / N_;
    int n = warp - m * N_;

    int blk = n >> 11;
    int boff = 0;
    for (int b = 0; b < blk; b++) boff += g_bsum[m * 16 + b];
    int end = g_off[m * (N_ + 1) + n + 1] + boff;
    int start;
    if (n == 0)                start = 0;
    else if ((n & 2047) == 0)  start = boff;
    else                       start = g_off[m * (N_ + 1) + n] + boff;

    float4 erd = *(const float4*)&g_er[(size_t)warp * 4];
    const int*    sl  = g_srcs + m * E_;
    const float*  elb = g_el  + (size_t)m * N_ * 4;
    constexpr size_t PLANE = (size_t)M_ * E_;
    float* ea0p = g_ea + 0 * PLANE + (size_t)m * E_;
    float* ea1p = g_ea + 1 * PLANE + (size_t)m * E_;
    float* ea2p = g_ea + 2 * PLANE + (size_t)m * E_;
    float* ea3p = g_ea + 3 * PLANE + (size_t)m * E_;
    const __half* fb  = g_feat + (size_t)m * N_ * HD_;

    // pass A: alphas into transposed planes + denominators
    float s0 = 0, s1 = 0, s2 = 0, s3 = 0;
    for (int i = start + lane; i < end; i += 32) {
        float4 e4 = *(const float4*)&elb[(size_t)sl[i] * 4];
        float p0 = __expf(lrelu(e4.x + erd.x));
        float p1 = __expf(lrelu(e4.y + erd.y));
        float p2 = __expf(lrelu(e4.z + erd.z));
        float p3 = __expf(lrelu(e4.w + erd.w));
        s0 += p0; s1 += p1; s2 += p2; s3 += p3;
        ea0p[i] = p0; ea1p[i] = p1; ea2p[i] = p2; ea3p[i] = p3;
    }
#pragma unroll
    for (int s = 16; s > 0; s >>= 1) {
        s0 += __shfl_xor_sync(0xffffffffu, s0, s);
        s1 += __shfl_xor_sync(0xffffffffu, s1, s);
        s2 += __shfl_xor_sync(0xffffffffu, s2, s);
        s3 += __shfl_xor_sync(0xffffffffu, s3, s);
    }
    int hsel = lane >> 3;           // head for this lane's 8 contiguous cols
    float r_s = hsel == 0 ? 1.f / fmaxf(s0, 1e-9f)
              : hsel == 1 ? 1.f / fmaxf(s1, 1e-9f)
              : hsel == 2 ? 1.f / fmaxf(s2, 1e-9f)
              :             1.f / fmaxf(s3, 1e-9f);
    const float* ab = hsel == 0 ? ea0p : hsel == 1 ? ea1p : hsel == 2 ? ea2p : ea3p;
    int colA = lane << 3;
    const __half* fbc = fb + colA;

    // pass B: unroll x4, 32-bit offsets, unnormalized alphas (normalize once below)
    float acc[8] = {0, 0, 0, 0, 0, 0, 0, 0};
    int i = start;
    for (; i + 4 <= end; i += 4) {
        float a0 = ab[i];
        float a1 = ab[i + 1];
        float a2 = ab[i + 2];
        float a3 = ab[i + 3];
        int sA = sl[i], sB = sl[i + 1], sC = sl[i + 2], sD = sl[i + 3];
        uint4 u0 = *(const uint4*)(fbc + (sA << 8));
        uint4 u1 = *(const uint4*)(fbc + (sB << 8));
        uint4 u2 = *(const uint4*)(fbc + (sC << 8));
        uint4 u3 = *(const uint4*)(fbc + (sD << 8));
        addmul8(acc, a0, u0);
        addmul8(acc, a1, u1);
        addmul8(acc, a2, u2);
        addmul8(acc, a3, u3);
    }
    for (; i < end; i++) {
        float a0 = ab[i];
        uint4 u0 = *(const uint4*)(fbc + (sl[i] << 8));
        addmul8(acc, a0, u0);
    }

    const float* brow = bias + m * HD_ + colA;
    float4 b0 = *(const float4*)brow;
    float4 b1 = *(const float4*)(brow + 4);
    acc[0] = acc[0] * r_s + b0.x; acc[1] = acc[1] * r_s + b0.y;
    acc[2] = acc[2] * r_s + b0.z; acc[3] = acc[3] * r_s + b0.w;
    acc[4] = acc[4] * r_s + b1.x; acc[5] = acc[5] * r_s + b1.y;
    acc[6] = acc[6] * r_s + b1.z; acc[7] = acc[7] * r_s + b1.w;

    __half* zb = g_z + (size_t)warp * HD_ + colA;
    *(uint4*)zb = make_uint4(
        h2u(__floats2half2_rn(acc[0], acc[1])), h2u(__floats2half2_rn(acc[2], acc[3])),
        h2u(__floats2half2_rn(acc[4], acc[5])), h2u(__floats2half2_rn(acc[6], acc[7])));
}

// ---------------- final mix (beta computed inline per block) ----------------
__global__ void final_kernel(float* __restrict__ out) {
    __shared__ float sb[3];
    if (threadIdx.x == 0) {
        float w0 = g_wsum[0] / (float)N_;
        float w1 = g_wsum[1] / (float)N_;
        float w2 = g_wsum[2] / (float)N_;
        float mx = fmaxf(w0, fmaxf(w1, w2));
        float e0 = expf(w0 - mx), e1 = expf(w1 - mx), e2 = expf(w2 - mx);
        float s = e0 + e1 + e2;
        sb[0] = e0 / s; sb[1] = e1 / s; sb[2] = e2 / s;
    }
    __syncthreads();
    int i = blockIdx.x * blockDim.x + threadIdx.x;   // one uint4 = 8 halves
    constexpr int S = N_ * HD_ / 8;
    if (i < M_ * N_) {
        // re-zero el/er/deg for the next replay (last readers: agg / hist)
        float4 z4 = make_float4(0.f, 0.f, 0.f, 0.f);
        *(float4*)&g_el[(size_t)i * 4] = z4;
        *(float4*)&g_er[(size_t)i * 4] = z4;
        g_deg[i] = 0;
    }
    if (i >= S) return;
    float b0 = sb[0], b1 = sb[1], b2 = sb[2];
    const uint4* zp = (const uint4*)g_z;
    uint4 u0 = zp[i], u1 = zp[i + S], u2 = zp[i + 2 * S];
    const __half2* h0 = (const __half2*)&u0;
    const __half2* h1 = (const __half2*)&u1;
    const __half2* h2 = (const __half2*)&u2;
    float r[8];
#pragma unroll
    for (int j = 0; j < 4; j++) {
        float2 x0 = __half22float2(h0[j]);
        float2 x1 = __half22float2(h1[j]);
        float2 x2 = __half22float2(h2[j]);
        r[2 * j]     = b0 * x0.x + b1 * x1.x + b2 * x2.x;
        r[2 * j + 1] = b0 * x0.y + b1 * x1.y + b2 * x2.y;
    }
    float4* op = (float4*)(out + (size_t)i * 8);
    op[0] = make_float4(r[0], r[1], r[2], r[3]);
    op[1] = make_float4(r[4], r[5], r[6], r[7]);
}

// ---------------- launch ----------------
extern "C" void kernel_launch(void* const* d_in, const int* in_sizes, int n_in,
                              void* d_out, int out_size) {
    const float* h      = (const float*)d_in[0];
    const int*   src    = (const int*)d_in[1];
    const int*   dst    = (const int*)d_in[2];
    const float* W      = (const float*)d_in[3];
    const float* attn_l = (const float*)d_in[4];
    const float* attn_r = (const float*)d_in[5];
    const float* bias   = (const float*)d_in[6];
    const float* sem_W1 = (const float*)d_in[7];
    const float* sem_b1 = (const float*)d_in[8];
    const float* sem_W2 = (const float*)d_in[9];
    float* out = (float*)d_out;

    __half *feat, *z, *hh;
    cudaGetSymbolAddress((void**)&feat, g_feat);
    cudaGetSymbolAddress((void**)&z, g_z);
    cudaGetSymbolAddress((void**)&hh, g_hh);

    // h -> fp16 (bit-identical to the in-GEMM quantization)
    convert_h_kernel<<<(N_ * IN_ / 4 + 255) / 256, 256>>>(h);

    // GEMM1 (BN=128, fp16 A, fused el/er + overlapped edge histogram)
    constexpr int NBX = (N_ + 127) / 128;       // 157
    constexpr int NBY = HD_ / 128;              // 2
    constexpr int GEMM1_BLOCKS = NBX * NBY * M_;
    constexpr int HIST_BLOCKS  = (M_ * E_ + 255) / 256;
    gemm_tc_kernel<128><<<GEMM1_BLOCKS + HIST_BLOCKS, 256>>>(
        nullptr, hh, W, feat, N_, IN_, HD_,
        0L, (long)IN_ * HD_, (long)N_ * HD_, nullptr, nullptr,
        attn_l, attn_r, dst, NBX, NBY);

    // scan + scatter fused (software grid barrier, 2 blocks/SM co-resident)
    csr_kernel<<<CSR_BLOCKS, 256>>>(src, dst);

    agg_kernel<<<(M_ * N_ * 32 + 255) / 256, 256>>>(bias);

    // GEMM2 (BN=128, fp16 A, fused): wsum[m] += sum tanh(z@W1+b1) . W2
    gemm_tc_kernel<128><<<dim3((M_ * N_ + 127) / 128, 1, 1), 256>>>(
        nullptr, z, sem_W1, nullptr, M_ * N_, HD_, HID_,
        0L, 0L, 0L, sem_b1, sem_W2, nullptr, nullptr, nullptr, 0, 0);

    final_kernel<<<(N_ * HD_ / 8 + 255) / 256, 256>>>(out);
}

// round 16
// speedup vs baseline: 1.0190x; 1.0190x over previous
#include <cuda_runtime.h>
#include <cuda_fp16.h>

static constexpr int N_   = 20000;
static constexpr int E_   = 320000;
static constexpr int M_   = 3;
static constexpr int IN_  = 128;
static constexpr int H_   = 4;
static constexpr int D_   = 64;
static constexpr int HD_  = 256;   // H*D
static constexpr int HID_ = 128;

// ---------------- scratch (device globals; no runtime allocation) ----------------
// Invariant: g_deg, g_el, g_er, g_wsum are ZERO on entry and are re-zeroed by the
// pipeline after their last use (final / final / scan1) so every replay is identical.
__device__ __half g_feat[(size_t)M_ * N_ * HD_];  // 30.7 MB fp16
__device__ __half g_z   [(size_t)M_ * N_ * HD_];  // 30.7 MB fp16
__device__ __half g_hh  [(size_t)N_ * IN_];       // 5.1 MB fp16 copy of h
__device__ float  g_el  [(size_t)M_ * N_ * H_];
__device__ float  g_er  [(size_t)M_ * N_ * H_];
__device__ float  g_ea  [(size_t)H_ * M_ * E_];   // alphas, HEAD-TRANSPOSED planes
__device__ int    g_deg [M_ * N_];
__device__ int    g_off [M_ * (N_ + 1)];          // RAW per-2048-block inclusive scan
__device__ int    g_rank[M_ * E_];                // edge rank within its dst (from hist)
__device__ int    g_srcs[M_ * E_];
__device__ int    g_bsum[M_ * 16];
__device__ float  g_wsum[M_];

__device__ __forceinline__ float lrelu(float x) { return x > 0.f ? x : 0.2f * x; }
__device__ __forceinline__ float fast_tanh(float x) {
    float y; asm("tanh.approx.f32 %0, %1;" : "=f"(y) : "f"(x)); return y;
}

// ---------------- tensor-core helpers ----------------
__device__ __forceinline__ void ldsm_x4(unsigned& r0, unsigned& r1, unsigned& r2, unsigned& r3,
                                        const void* p) {
    unsigned addr = (unsigned)__cvta_generic_to_shared(p);
    asm volatile("ldmatrix.sync.aligned.m8n8.x4.shared.b16 {%0,%1,%2,%3}, [%4];"
                 : "=r"(r0), "=r"(r1), "=r"(r2), "=r"(r3) : "r"(addr));
}
__device__ __forceinline__ void ldsm_x4_t(unsigned& r0, unsigned& r1, unsigned& r2, unsigned& r3,
                                          const void* p) {
    unsigned addr = (unsigned)__cvta_generic_to_shared(p);
    asm volatile("ldmatrix.sync.aligned.m8n8.x4.trans.shared.b16 {%0,%1,%2,%3}, [%4];"
                 : "=r"(r0), "=r"(r1), "=r"(r2), "=r"(r3) : "r"(addr));
}
__device__ __forceinline__ void mma16816(float* c, const unsigned* a, const unsigned* b) {
    asm volatile("mma.sync.aligned.m16n8k16.row.col.f32.f16.f16.f32 "
                 "{%0,%1,%2,%3}, {%4,%5,%6,%7}, {%8,%9}, {%0,%1,%2,%3};"
                 : "+f"(c[0]), "+f"(c[1]), "+f"(c[2]), "+f"(c[3])
                 : "r"(a[0]), "r"(a[1]), "r"(a[2]), "r"(a[3]), "r"(b[0]), "r"(b[1]));
}
__device__ __forceinline__ unsigned h2u(__half2 h) { return *reinterpret_cast<unsigned*>(&h); }
__device__ __forceinline__ uint4 pack8(float4 a, float4 b) {
    uint4 r;
    r.x = h2u(__floats2half2_rn(a.x, a.y));
    r.y = h2u(__floats2half2_rn(a.z, a.w));
    r.z = h2u(__floats2half2_rn(b.x, b.y));
    r.w = h2u(__floats2half2_rn(b.z, b.w));
    return r;
}

// ---------------- h fp32 -> fp16 (bit-identical to pack8 quantization) -----------
__global__ void convert_h_kernel(const float* __restrict__ h) {
    int i = blockIdx.x * blockDim.x + threadIdx.x;   // one float4 -> 4 halves
    constexpr int S = N_ * IN_ / 4;
    if (i >= S) return;
    float4 f = ((const float4*)h)[i];
    __half2 h0 = __floats2half2_rn(f.x, f.y);
    __half2 h1 = __floats2half2_rn(f.z, f.w);
    ((uint2*)g_hh)[i] = make_uint2(h2u(h0), h2u(h1));
}

// ---------------- tensor-core GEMM: BM=128,BN(64|128),BK=32, 8 warps -------------
// A from fp32 (A) or fp16 (Ah).  Epilogues:
//   Ch != nullptr : store fp16 C AND fused el/er partial dots (GEMM1)
//   W2 != nullptr : fused wsum[m] += sum tanh(acc+bias)*W2, no store (GEMM2)
// hdst != nullptr : 1-D launch; blocks beyond nbx*nby*M_ do the edge histogram
//                   AND record each edge's rank within its dst node.
template <int BN>
__global__ __launch_bounds__(256) void gemm_tc_kernel(
    const float* __restrict__ A, const __half* __restrict__ Ah,
    const float* __restrict__ B, __half* __restrict__ Ch,
    int Mrows, int K, int Ncols,
    long aStride, long bStride, long cStride,
    const float* __restrict__ bias, const float* __restrict__ W2,
    const float* __restrict__ attL, const float* __restrict__ attR,
    const int* __restrict__ hdst, int nbx, int nby)
{
    constexpr int BM = 128, BK = 32;
    constexpr int NT = BN / 16;        // 8-col mma tiles per warp (n)
    __shared__ __half As[BM][BK + 8];
    __shared__ __half Bs[BK][BN + 8];
    __shared__ float red[4];

    int bxi, byi, bzi;
    if (hdst) {
        int G = nbx * nby * M_;
        int b = blockIdx.x;
        if (b >= G) {               // histogram block: one edge per thread
            int i = (b - G) * 256 + threadIdx.x;
            if (i < M_ * E_)
                g_rank[i] = atomicAdd(&g_deg[(i / E_) * N_ + hdst[i]], 1);
            return;
        }
        bxi = b % nbx; byi = (b / nbx) % nby; bzi = b / (nbx * nby);
    } else {
        bxi = blockIdx.x; byi = blockIdx.y; bzi = blockIdx.z;
    }

    if (A) A += (long)bzi * aStride;
    B += (long)bzi * bStride;
    if (Ch) Ch += (long)bzi * cStride;

    int tid  = threadIdx.x;
    int lane = tid & 31, warp = tid >> 5;
    int wm = (warp & 3) * 32;
    int wn = (warp >> 2) * (BN / 2);
    int rowBase = bxi * BM, colBase = byi * BN;

    float acc[2][NT][4];
#pragma unroll
    for (int mt = 0; mt < 2; mt++)
#pragma unroll
        for (int nt = 0; nt < NT; nt++)
#pragma unroll
            for (int j = 0; j < 4; j++) acc[mt][nt][j] = 0.f;

    int arow = tid >> 1, acb = (tid & 1) * 16;
    int brow = tid >> 3, bcb = (tid & 7) * (BN / 8);
    bool aValid = (rowBase + arow) < Mrows;
    const float*  Abase  = A  ? A  + (long)(rowBase + arow) * K + acb : nullptr;
    const __half* Ahbase = Ah ? Ah + (long)(rowBase + arow) * K + acb : nullptr;
    const float*  Bbase  = B + (long)brow * Ncols + colBase + bcb;

    for (int k0 = 0; k0 < K; k0 += BK) {
        if (Ah) {
            uint4 q0 = make_uint4(0, 0, 0, 0), q1 = q0;
            if (aValid) {
                const __half* p = Ahbase + k0;
                q0 = *(const uint4*)p;
                q1 = *(const uint4*)(p + 8);
            }
            *(uint4*)&As[arow][acb]     = q0;
            *(uint4*)&As[arow][acb + 8] = q1;
        } else {
            float4 f0 = make_float4(0, 0, 0, 0), f1 = f0, f2 = f0, f3 = f0;
            if (aValid) {
                const float* p = Abase + k0;
                f0 = *(const float4*)(p + 0);  f1 = *(const float4*)(p + 4);
                f2 = *(const float4*)(p + 8);  f3 = *(const float4*)(p + 12);
            }
            *(uint4*)&As[arow][acb]     = pack8(f0, f1);
            *(uint4*)&As[arow][acb + 8] = pack8(f2, f3);
        }
        {
            const float* p = Bbase + (long)k0 * Ncols;
            float4 g0 = *(const float4*)(p + 0);
            float4 g1 = *(const float4*)(p + 4);
            *(uint4*)&Bs[brow][bcb] = pack8(g0, g1);
            if (BN == 128) {
                float4 g2 = *(const float4*)(p + 8);
                float4 g3 = *(const float4*)(p + 12);
                *(uint4*)&Bs[brow][bcb + 8] = pack8(g2, g3);
            }
        }
        __syncthreads();

#pragma unroll
        for (int kk = 0; kk < BK; kk += 16) {
            unsigned a[2][4], b[NT][2];
#pragma unroll
            for (int mt = 0; mt < 2; mt++)
                ldsm_x4(a[mt][0], a[mt][1], a[mt][2], a[mt][3],
                        &As[wm + mt * 16 + (lane & 15)][kk + (lane >> 4) * 8]);
#pragma unroll
            for (int np = 0; np < BN / 32; np++) {
                unsigned r0, r1, r2, r3;
                ldsm_x4_t(r0, r1, r2, r3,
                          &Bs[kk + (lane & 15)][wn + np * 16 + (lane >> 4) * 8]);
                b[2 * np][0] = r0; b[2 * np][1] = r1;
                b[2 * np + 1][0] = r2; b[2 * np + 1][1] = r3;
            }
#pragma unroll
            for (int mt = 0; mt < 2; mt++)
#pragma unroll
                for (int nt = 0; nt < NT; nt++)
                    mma16816(acc[mt][nt], a[mt], b[nt]);
        }
        __syncthreads();
    }

    bool fusedW2 = (W2 != nullptr);
    if (fusedW2) {
        if (tid < 4) red[tid] = 0.f;
        __syncthreads();
    }

    int gid = lane >> 2, tig = lane & 3;
    int head = (colBase + wn) >> 6;                // warp's 64-col slice = one head
    const float* al = attL ? attL + bzi * HD_ + colBase : nullptr;
    const float* ar = attL ? attR + bzi * HD_ + colBase : nullptr;

#pragma unroll
    for (int mt = 0; mt < 2; mt++) {
#pragma unroll
        for (int half = 0; half < 2; half++) {
            int row = rowBase + wm + mt * 16 + gid + half * 8;
            bool rv = row < Mrows;
            if (fusedW2) {
                if (rv) {
                    int m = row / N_;
                    float s = 0.f;
#pragma unroll
                    for (int nt = 0; nt < NT; nt++) {
                        int col = colBase + wn + nt * 8 + tig * 2;
                        s += fast_tanh(acc[mt][nt][2 * half] + bias[col]) * W2[col];
                        s += fast_tanh(acc[mt][nt][2 * half + 1] + bias[col + 1]) * W2[col + 1];
                    }
                    atomicAdd(&red[m], s);
                }
            } else {
                if (rv) {
                    __half* cp = Ch + (long)row * Ncols + colBase + wn + tig * 2;
#pragma unroll
                    for (int nt = 0; nt < NT; nt++) {
                        __half2 v = __floats2half2_rn(acc[mt][nt][2 * half],
                                                      acc[mt][nt][2 * half + 1]);
                        *(__half2*)(cp + nt * 8) = v;
                    }
                }
                if (al) {
                    float sel = 0.f, ser = 0.f;
#pragma unroll
                    for (int nt = 0; nt < NT; nt++) {
                        int cl = wn + nt * 8 + tig * 2;
                        float v0 = acc[mt][nt][2 * half], v1 = acc[mt][nt][2 * half + 1];
                        sel += v0 * al[cl] + v1 * al[cl + 1];
                        ser += v0 * ar[cl] + v1 * ar[cl + 1];
                    }
                    sel += __shfl_xor_sync(0xffffffffu, sel, 1);
                    sel += __shfl_xor_sync(0xffffffffu, sel, 2);
                    ser += __shfl_xor_sync(0xffffffffu, ser, 1);
                    ser += __shfl_xor_sync(0xffffffffu, ser, 2);
                    if (rv && tig == 0) {
                        size_t idx = ((size_t)bzi * N_ + row) * 4 + head;
                        atomicAdd(&g_el[idx], sel);
                        atomicAdd(&g_er[idx], ser);
                    }
                }
            }
        }
    }
    if (fusedW2) {
        __syncthreads();
        if (tid < 3) atomicAdd(&g_wsum[tid], red[tid]);
    }
}

// ---------------- CSR build: per-2048-block scan; boff applied inline downstream --
__global__ void scan1_kernel() {   // grid (10, M_), 2048 nodes/block
    int m = blockIdx.y, b = blockIdx.x, t = threadIdx.x;
    if (m == 0 && b == 0 && t == 0) {               // pre-GEMM2 zero
        g_wsum[0] = 0.f; g_wsum[1] = 0.f; g_wsum[2] = 0.f;
    }
    int i0 = b * 2048 + t * 8;
    int v[8];
    int s = 0;
#pragma unroll
    for (int j = 0; j < 8; j++) {
        int i = i0 + j;
        int d = (i < N_) ? g_deg[m * N_ + i] : 0;
        s += d; v[j] = s;
    }
    __shared__ int sh[256];
    sh[t] = s;
    __syncthreads();
#pragma unroll
    for (int st = 1; st < 256; st <<= 1) {
        int y = (t >= st) ? sh[t - st] : 0;
        __syncthreads();
        sh[t] += y;
        __syncthreads();
    }
    int excl = sh[t] - s;
#pragma unroll
    for (int j = 0; j < 8; j++) {
        int i = i0 + j;
        if (i < N_) g_off[m * (N_ + 1) + i + 1] = excl + v[j];
    }
    if (t == 255) g_bsum[m * 16 + b] = sh[255];
}

// ---------------- scatter (atomic-free; 4 independent edge chains per thread) ----
__global__ __launch_bounds__(256) void scatter_kernel(const int* __restrict__ src,
                                                      const int* __restrict__ dst) {
    __shared__ int sboff[M_ * 16];
    int t = threadIdx.x;
    if (t < M_ * 16) {
        int m = t >> 4, b = t & 15;
        int s = 0;
        for (int k = 0; k < b; k++) s += g_bsum[m * 16 + k];
        sboff[t] = s;
    }
    __syncthreads();

    int t0 = blockIdx.x * 1024;
    int dd[4], rk[4], sr[4], mm[4], off[4];
    bool val[4];
#pragma unroll
    for (int j = 0; j < 4; j++) {
        int i = t0 + t + j * 256;
        val[j] = i < M_ * E_;
        if (val[j]) {
            dd[j] = dst[i];
            rk[j] = g_rank[i];
            sr[j] = src[i];
            mm[j] = i / E_;
        }
    }
#pragma unroll
    for (int j = 0; j < 4; j++)
        if (val[j] && dd[j] != 0)
            off[j] = g_off[mm[j] * (N_ + 1) + dd[j]];
#pragma unroll
    for (int j = 0; j < 4; j++) {
        if (!val[j]) continue;
        int pos;
        if (dd[j] == 0) {
            pos = rk[j];
        } else {
            int blk = (dd[j] - 1) >> 11;
            pos = off[j] + sboff[mm[j] * 16 + blk] + rk[j];
        }
        g_srcs[mm[j] * E_ + pos] = sr[j];
    }
}

// ---------------- GAT aggregate: one warp per (metapath, dst) -------------------
// pass A: exp once per (edge,head) -> 4 head-transposed alpha planes + denominators
// pass B: serial edges, unroll x4, scalar UNNORMALIZED alpha loads; normalize at end
__device__ __forceinline__ void addmul8(float* acc, float a, uint4 u) {
    const __half2* hp = (const __half2*)&u;
#pragma unroll
    for (int j = 0; j < 4; j++) {
        float2 x = __half22float2(hp[j]);
        acc[2 * j]     += a * x.x;
        acc[2 * j + 1] += a * x.y;
    }
}

__global__ __launch_bounds__(256) void agg_kernel(const float* __restrict__ bias) {
    int g = blockIdx.x * blockDim.x + threadIdx.x;
    int warp = g >> 5, lane = g & 31;
    if (warp >= M_ * N_) return;
    int m = warp / N_;
    int n = warp - m * N_;

    int blk = n >> 11;
    int boff = 0;
    for (int b = 0; b < blk; b++) boff += g_bsum[m * 16 + b];
    int end = g_off[m * (N_ + 1) + n + 1] + boff;
    int start;
    if (n == 0)                start = 0;
    else if ((n & 2047) == 0)  start = boff;
    else                       start = g_off[m * (N_ + 1) + n] + boff;

    float4 erd = *(const float4*)&g_er[(size_t)warp * 4];
    const int*    sl  = g_srcs + m * E_;
    const float*  elb = g_el  + (size_t)m * N_ * 4;
    constexpr size_t PLANE = (size_t)M_ * E_;
    float* ea0p = g_ea + 0 * PLANE + (size_t)m * E_;
    float* ea1p = g_ea + 1 * PLANE + (size_t)m * E_;
    float* ea2p = g_ea + 2 * PLANE + (size_t)m * E_;
    float* ea3p = g_ea + 3 * PLANE + (size_t)m * E_;
    const __half* fb  = g_feat + (size_t)m * N_ * HD_;

    // pass A: alphas into transposed planes + denominators
    float s0 = 0, s1 = 0, s2 = 0, s3 = 0;
    for (int i = start + lane; i < end; i += 32) {
        float4 e4 = *(const float4*)&elb[(size_t)sl[i] * 4];
        float p0 = __expf(lrelu(e4.x + erd.x));
        float p1 = __expf(lrelu(e4.y + erd.y));
        float p2 = __expf(lrelu(e4.z + erd.z));
        float p3 = __expf(lrelu(e4.w + erd.w));
        s0 += p0; s1 += p1; s2 += p2; s3 += p3;
        ea0p[i] = p0; ea1p[i] = p1; ea2p[i] = p2; ea3p[i] = p3;
    }
#pragma unroll
    for (int s = 16; s > 0; s >>= 1) {
        s0 += __shfl_xor_sync(0xffffffffu, s0, s);
        s1 += __shfl_xor_sync(0xffffffffu, s1, s);
        s2 += __shfl_xor_sync(0xffffffffu, s2, s);
        s3 += __shfl_xor_sync(0xffffffffu, s3, s);
    }
    int hsel = lane >> 3;           // head for this lane's 8 contiguous cols
    float r_s = hsel == 0 ? 1.f / fmaxf(s0, 1e-9f)
              : hsel == 1 ? 1.f / fmaxf(s1, 1e-9f)
              : hsel == 2 ? 1.f / fmaxf(s2, 1e-9f)
              :             1.f / fmaxf(s3, 1e-9f);
    const float* ab = hsel == 0 ? ea0p : hsel == 1 ? ea1p : hsel == 2 ? ea2p : ea3p;
    int colA = lane << 3;
    const __half* fbc = fb + colA;

    // pass B: unroll x4, 32-bit offsets, unnormalized alphas (normalize once below)
    float acc[8] = {0, 0, 0, 0, 0, 0, 0, 0};
    int i = start;
    for (; i + 4 <= end; i += 4) {
        float a0 = ab[i];
        float a1 = ab[i + 1];
        float a2 = ab[i + 2];
        float a3 = ab[i + 3];
        int sA = sl[i], sB = sl[i + 1], sC = sl[i + 2], sD = sl[i + 3];
        uint4 u0 = *(const uint4*)(fbc + (sA << 8));
        uint4 u1 = *(const uint4*)(fbc + (sB << 8));
        uint4 u2 = *(const uint4*)(fbc + (sC << 8));
        uint4 u3 = *(const uint4*)(fbc + (sD << 8));
        addmul8(acc, a0, u0);
        addmul8(acc, a1, u1);
        addmul8(acc, a2, u2);
        addmul8(acc, a3, u3);
    }
    for (; i < end; i++) {
        float a0 = ab[i];
        uint4 u0 = *(const uint4*)(fbc + (sl[i] << 8));
        addmul8(acc, a0, u0);
    }

    const float* brow = bias + m * HD_ + colA;
    float4 b0 = *(const float4*)brow;
    float4 b1 = *(const float4*)(brow + 4);
    acc[0] = acc[0] * r_s + b0.x; acc[1] = acc[1] * r_s + b0.y;
    acc[2] = acc[2] * r_s + b0.z; acc[3] = acc[3] * r_s + b0.w;
    acc[4] = acc[4] * r_s + b1.x; acc[5] = acc[5] * r_s + b1.y;
    acc[6] = acc[6] * r_s + b1.z; acc[7] = acc[7] * r_s + b1.w;

    __half* zb = g_z + (size_t)warp * HD_ + colA;
    *(uint4*)zb = make_uint4(
        h2u(__floats2half2_rn(acc[0], acc[1])), h2u(__floats2half2_rn(acc[2], acc[3])),
        h2u(__floats2half2_rn(acc[4], acc[5])), h2u(__floats2half2_rn(acc[6], acc[7])));
}

// ---------------- final mix (beta computed inline per block) ----------------
__global__ void final_kernel(float* __restrict__ out) {
    __shared__ float sb[3];
    if (threadIdx.x == 0) {
        float w0 = g_wsum[0] / (float)N_;
        float w1 = g_wsum[1] / (float)N_;
        float w2 = g_wsum[2] / (float)N_;
        float mx = fmaxf(w0, fmaxf(w1, w2));
        float e0 = expf(w0 - mx), e1 = expf(w1 - mx), e2 = expf(w2 - mx);
        float s = e0 + e1 + e2;
        sb[0] = e0 / s; sb[1] = e1 / s; sb[2] = e2 / s;
    }
    __syncthreads();
    int i = blockIdx.x * blockDim.x + threadIdx.x;   // one uint4 = 8 halves
    constexpr int S = N_ * HD_ / 8;
    if (i < M_ * N_) {
        // re-zero el/er/deg for the next replay (last readers: agg / hist)
        float4 z4 = make_float4(0.f, 0.f, 0.f, 0.f);
        *(float4*)&g_el[(size_t)i * 4] = z4;
        *(float4*)&g_er[(size_t)i * 4] = z4;
        g_deg[i] = 0;
    }
    if (i >= S) return;
    float b0 = sb[0], b1 = sb[1], b2 = sb[2];
    const uint4* zp = (const uint4*)g_z;
    uint4 u0 = zp[i], u1 = zp[i + S], u2 = zp[i + 2 * S];
    const __half2* h0 = (const __half2*)&u0;
    const __half2* h1 = (const __half2*)&u1;
    const __half2* h2 = (const __half2*)&u2;
    float r[8];
#pragma unroll
    for (int j = 0; j < 4; j++) {
        float2 x0 = __half22float2(h0[j]);
        float2 x1 = __half22float2(h1[j]);
        float2 x2 = __half22float2(h2[j]);
        r[2 * j]     = b0 * x0.x + b1 * x1.x + b2 * x2.x;
        r[2 * j + 1] = b0 * x0.y + b1 * x1.y + b2 * x2.y;
    }
    float4* op = (float4*)(out + (size_t)i * 8);
    op[0] = make_float4(r[0], r[1], r[2], r[3]);
    op[1] = make_float4(r[4], r[5], r[6], r[7]);
}

// ---------------- launch ----------------
extern "C" void kernel_launch(void* const* d_in, const int* in_sizes, int n_in,
                              void* d_out, int out_size) {
    const float* h      = (const float*)d_in[0];
    const int*   src    = (const int*)d_in[1];
    const int*   dst    = (const int*)d_in[2];
    const float* W      = (const float*)d_in[3];
    const float* attn_l = (const float*)d_in[4];
    const float* attn_r = (const float*)d_in[5];
    const float* bias   = (const float*)d_in[6];
    const float* sem_W1 = (const float*)d_in[7];
    const float* sem_b1 = (const float*)d_in[8];
    const float* sem_W2 = (const float*)d_in[9];
    float* out = (float*)d_out;

    __half *feat, *z, *hh;
    cudaGetSymbolAddress((void**)&feat, g_feat);
    cudaGetSymbolAddress((void**)&z, g_z);
    cudaGetSymbolAddress((void**)&hh, g_hh);

    // h -> fp16 (bit-identical to the in-GEMM quantization)
    convert_h_kernel<<<(N_ * IN_ / 4 + 255) / 256, 256>>>(h);

    // GEMM1 (BN=128, fp16 A, fused el/er + overlapped edge histogram)
    constexpr int NBX = (N_ + 127) / 128;       // 157
    constexpr int NBY = HD_ / 128;              // 2
    constexpr int GEMM1_BLOCKS = NBX * NBY * M_;
    constexpr int HIST_BLOCKS  = (M_ * E_ + 255) / 256;
    gemm_tc_kernel<128><<<GEMM1_BLOCKS + HIST_BLOCKS, 256>>>(
        nullptr, hh, W, feat, N_, IN_, HD_,
        0L, (long)IN_ * HD_, (long)N_ * HD_, nullptr, nullptr,
        attn_l, attn_r, dst, NBX, NBY);

    scan1_kernel<<<dim3(10, M_), 256>>>();
    scatter_kernel<<<(M_ * E_ + 1023) / 1024, 256>>>(src, dst);

    agg_kernel<<<(M_ * N_ * 32 + 255) / 256, 256>>>(bias);

    // GEMM2 (BN=128, fp16 A, fused): wsum[m] += sum tanh(z@W1+b1) . W2
    gemm_tc_kernel<128><<<dim3((M_ * N_ + 127) / 128, 1, 1), 256>>>(
        nullptr, z, sem_W1, nullptr, M_ * N_, HD_, HID_,
        0L, 0L, 0L, sem_b1, sem_W2, nullptr, nullptr, nullptr, 0, 0);

    final_kernel<<<(N_ * HD_ / 8 + 255) / 256, 256>>>(out);
}

// round 17
// speedup vs baseline: 1.0211x; 1.0021x over previous
#include <cuda_runtime.h>
#include <cuda_fp16.h>

static constexpr int N_   = 20000;
static constexpr int E_   = 320000;
static constexpr int M_   = 3;
static constexpr int IN_  = 128;
static constexpr int H_   = 4;
static constexpr int D_   = 64;
static constexpr int HD_  = 256;   // H*D
static constexpr int HID_ = 128;

// ---------------- scratch (device globals; no runtime allocation) ----------------
// Invariant: g_deg, g_el, g_er, g_wsum are ZERO on entry and are re-zeroed by the
// pipeline after their last use (final / final / scan1) so every replay is identical.
__device__ __half g_feat[(size_t)M_ * N_ * HD_];  // 30.7 MB fp16
__device__ __half g_z   [(size_t)M_ * N_ * HD_];  // 30.7 MB fp16
__device__ __half g_hh  [(size_t)N_ * IN_];       // 5.1 MB fp16 copy of h
__device__ float  g_el  [(size_t)M_ * N_ * H_];
__device__ float  g_er  [(size_t)M_ * N_ * H_];
__device__ float  g_ea  [(size_t)H_ * M_ * E_];   // alphas, HEAD-TRANSPOSED planes
__device__ int    g_deg [M_ * N_];
__device__ int    g_off [M_ * (N_ + 1)];          // RAW per-2048-block inclusive scan
__device__ int    g_rank[M_ * E_];                // edge rank within its dst (from hist)
__device__ int    g_srcs[M_ * E_];
__device__ int    g_bsum[M_ * 16];
__device__ float  g_wsum[M_];

__device__ __forceinline__ float lrelu(float x) { return x > 0.f ? x : 0.2f * x; }
__device__ __forceinline__ float fast_tanh(float x) {
    float y; asm("tanh.approx.f32 %0, %1;" : "=f"(y) : "f"(x)); return y;
}

// ---------------- tensor-core helpers ----------------
__device__ __forceinline__ void ldsm_x4(unsigned& r0, unsigned& r1, unsigned& r2, unsigned& r3,
                                        const void* p) {
    unsigned addr = (unsigned)__cvta_generic_to_shared(p);
    asm volatile("ldmatrix.sync.aligned.m8n8.x4.shared.b16 {%0,%1,%2,%3}, [%4];"
                 : "=r"(r0), "=r"(r1), "=r"(r2), "=r"(r3) : "r"(addr));
}
__device__ __forceinline__ void ldsm_x4_t(unsigned& r0, unsigned& r1, unsigned& r2, unsigned& r3,
                                          const void* p) {
    unsigned addr = (unsigned)__cvta_generic_to_shared(p);
    asm volatile("ldmatrix.sync.aligned.m8n8.x4.trans.shared.b16 {%0,%1,%2,%3}, [%4];"
                 : "=r"(r0), "=r"(r1), "=r"(r2), "=r"(r3) : "r"(addr));
}
__device__ __forceinline__ void mma16816(float* c, const unsigned* a, const unsigned* b) {
    asm volatile("mma.sync.aligned.m16n8k16.row.col.f32.f16.f16.f32 "
                 "{%0,%1,%2,%3}, {%4,%5,%6,%7}, {%8,%9}, {%0,%1,%2,%3};"
                 : "+f"(c[0]), "+f"(c[1]), "+f"(c[2]), "+f"(c[3])
                 : "r"(a[0]), "r"(a[1]), "r"(a[2]), "r"(a[3]), "r"(b[0]), "r"(b[1]));
}
__device__ __forceinline__ unsigned h2u(__half2 h) { return *reinterpret_cast<unsigned*>(&h); }
__device__ __forceinline__ uint4 pack8(float4 a, float4 b) {
    uint4 r;
    r.x = h2u(__floats2half2_rn(a.x, a.y));
    r.y = h2u(__floats2half2_rn(a.z, a.w));
    r.z = h2u(__floats2half2_rn(b.x, b.y));
    r.w = h2u(__floats2half2_rn(b.z, b.w));
    return r;
}

// ---------------- h fp32 -> fp16 (bit-identical to pack8 quantization) -----------
__global__ void convert_h_kernel(const float* __restrict__ h) {
    int i = blockIdx.x * blockDim.x + threadIdx.x;   // one float4 -> 4 halves
    constexpr int S = N_ * IN_ / 4;
    if (i >= S) return;
    float4 f = ((const float4*)h)[i];
    __half2 h0 = __floats2half2_rn(f.x, f.y);
    __half2 h1 = __floats2half2_rn(f.z, f.w);
    ((uint2*)g_hh)[i] = make_uint2(h2u(h0), h2u(h1));
}

// ---------------- tensor-core GEMM: BM=128,BN(64|128),BK=32, 8 warps -------------
// A from fp32 (A) or fp16 (Ah).  Epilogues:
//   Ch != nullptr : store fp16 C AND fused el/er partial dots (GEMM1)
//   W2 != nullptr : fused wsum[m] += sum tanh(acc+bias)*W2, no store (GEMM2)
// hdst != nullptr : 1-D launch; blocks beyond nbx*nby*M_ do the edge histogram
//                   (16 edges per thread to minimize fat-block residency waves)
//                   AND record each edge's rank within its dst node.
template <int BN>
__global__ __launch_bounds__(256) void gemm_tc_kernel(
    const float* __restrict__ A, const __half* __restrict__ Ah,
    const float* __restrict__ B, __half* __restrict__ Ch,
    int Mrows, int K, int Ncols,
    long aStride, long bStride, long cStride,
    const float* __restrict__ bias, const float* __restrict__ W2,
    const float* __restrict__ attL, const float* __restrict__ attR,
    const int* __restrict__ hdst, int nbx, int nby)
{
    constexpr int BM = 128, BK = 32;
    constexpr int NT = BN / 16;        // 8-col mma tiles per warp (n)
    __shared__ __half As[BM][BK + 8];
    __shared__ __half Bs[BK][BN + 8];
    __shared__ float red[4];

    int bxi, byi, bzi;
    if (hdst) {
        int G = nbx * nby * M_;
        int b = blockIdx.x;
        if (b >= G) {               // histogram block: 16 edges per thread
            int base = (b - G) * 4096 + threadIdx.x;
#pragma unroll
            for (int j = 0; j < 16; j++) {
                int i = base + j * 256;
                if (i < M_ * E_)
                    g_rank[i] = atomicAdd(&g_deg[(i / E_) * N_ + hdst[i]], 1);
            }
            return;
        }
        bxi = b % nbx; byi = (b / nbx) % nby; bzi = b / (nbx * nby);
    } else {
        bxi = blockIdx.x; byi = blockIdx.y; bzi = blockIdx.z;
    }

    if (A) A += (long)bzi * aStride;
    B += (long)bzi * bStride;
    if (Ch) Ch += (long)bzi * cStride;

    int tid  = threadIdx.x;
    int lane = tid & 31, warp = tid >> 5;
    int wm = (warp & 3) * 32;
    int wn = (warp >> 2) * (BN / 2);
    int rowBase = bxi * BM, colBase = byi * BN;

    float acc[2][NT][4];
#pragma unroll
    for (int mt = 0; mt < 2; mt++)
#pragma unroll
        for (int nt = 0; nt < NT; nt++)
#pragma unroll
            for (int j = 0; j < 4; j++) acc[mt][nt][j] = 0.f;

    int arow = tid >> 1, acb = (tid & 1) * 16;
    int brow = tid >> 3, bcb = (tid & 7) * (BN / 8);
    bool aValid = (rowBase + arow) < Mrows;
    const float*  Abase  = A  ? A  + (long)(rowBase + arow) * K + acb : nullptr;
    const __half* Ahbase = Ah ? Ah + (long)(rowBase + arow) * K + acb : nullptr;
    const float*  Bbase  = B + (long)brow * Ncols + colBase + bcb;

    for (int k0 = 0; k0 < K; k0 += BK) {
        if (Ah) {
            uint4 q0 = make_uint4(0, 0, 0, 0), q1 = q0;
            if (aValid) {
                const __half* p = Ahbase + k0;
                q0 = *(const uint4*)p;
                q1 = *(const uint4*)(p + 8);
            }
            *(uint4*)&As[arow][acb]     = q0;
            *(uint4*)&As[arow][acb + 8] = q1;
        } else {
            float4 f0 = make_float4(0, 0, 0, 0), f1 = f0, f2 = f0, f3 = f0;
            if (aValid) {
                const float* p = Abase + k0;
                f0 = *(const float4*)(p + 0);  f1 = *(const float4*)(p + 4);
                f2 = *(const float4*)(p + 8);  f3 = *(const float4*)(p + 12);
            }
            *(uint4*)&As[arow][acb]     = pack8(f0, f1);
            *(uint4*)&As[arow][acb + 8] = pack8(f2, f3);
        }
        {
            const float* p = Bbase + (long)k0 * Ncols;
            float4 g0 = *(const float4*)(p + 0);
            float4 g1 = *(const float4*)(p + 4);
            *(uint4*)&Bs[brow][bcb] = pack8(g0, g1);
            if (BN == 128) {
                float4 g2 = *(const float4*)(p + 8);
                float4 g3 = *(const float4*)(p + 12);
                *(uint4*)&Bs[brow][bcb + 8] = pack8(g2, g3);
            }
        }
        __syncthreads();

#pragma unroll
        for (int kk = 0; kk < BK; kk += 16) {
            unsigned a[2][4], b[NT][2];
#pragma unroll
            for (int mt = 0; mt < 2; mt++)
                ldsm_x4(a[mt][0], a[mt][1], a[mt][2], a[mt][3],
                        &As[wm + mt * 16 + (lane & 15)][kk + (lane >> 4) * 8]);
#pragma unroll
            for (int np = 0; np < BN / 32; np++) {
                unsigned r0, r1, r2, r3;
                ldsm_x4_t(r0, r1, r2, r3,
                          &Bs[kk + (lane & 15)][wn + np * 16 + (lane >> 4) * 8]);
                b[2 * np][0] = r0; b[2 * np][1] = r1;
                b[2 * np + 1][0] = r2; b[2 * np + 1][1] = r3;
            }
#pragma unroll
            for (int mt = 0; mt < 2; mt++)
#pragma unroll
                for (int nt = 0; nt < NT; nt++)
                    mma16816(acc[mt][nt], a[mt], b[nt]);
        }
        __syncthreads();
    }

    bool fusedW2 = (W2 != nullptr);
    if (fusedW2) {
        if (tid < 4) red[tid] = 0.f;
        __syncthreads();
    }

    int gid = lane >> 2, tig = lane & 3;
    int head = (colBase + wn) >> 6;                // warp's 64-col slice = one head
    const float* al = attL ? attL + bzi * HD_ + colBase : nullptr;
    const float* ar = attL ? attR + bzi * HD_ + colBase : nullptr;

#pragma unroll
    for (int mt = 0; mt < 2; mt++) {
#pragma unroll
        for (int half = 0; half < 2; half++) {
            int row = rowBase + wm + mt * 16 + gid + half * 8;
            bool rv = row < Mrows;
            if (fusedW2) {
                if (rv) {
                    int m = row / N_;
                    float s = 0.f;
#pragma unroll
                    for (int nt = 0; nt < NT; nt++) {
                        int col = colBase + wn + nt * 8 + tig * 2;
                        s += fast_tanh(acc[mt][nt][2 * half] + bias[col]) * W2[col];
                        s += fast_tanh(acc[mt][nt][2 * half + 1] + bias[col + 1]) * W2[col + 1];
                    }
                    atomicAdd(&red[m], s);
                }
            } else {
                if (rv) {
                    __half* cp = Ch + (long)row * Ncols + colBase + wn + tig * 2;
#pragma unroll
                    for (int nt = 0; nt < NT; nt++) {
                        __half2 v = __floats2half2_rn(acc[mt][nt][2 * half],
                                                      acc[mt][nt][2 * half + 1]);
                        *(__half2*)(cp + nt * 8) = v;
                    }
                }
                if (al) {
                    float sel = 0.f, ser = 0.f;
#pragma unroll
                    for (int nt = 0; nt < NT; nt++) {
                        int cl = wn + nt * 8 + tig * 2;
                        float v0 = acc[mt][nt][2 * half], v1 = acc[mt][nt][2 * half + 1];
                        sel += v0 * al[cl] + v1 * al[cl + 1];
                        ser += v0 * ar[cl] + v1 * ar[cl + 1];
                    }
                    sel += __shfl_xor_sync(0xffffffffu, sel, 1);
                    sel += __shfl_xor_sync(0xffffffffu, sel, 2);
                    ser += __shfl_xor_sync(0xffffffffu, ser, 1);
                    ser += __shfl_xor_sync(0xffffffffu, ser, 2);
                    if (rv && tig == 0) {
                        size_t idx = ((size_t)bzi * N_ + row) * 4 + head;
                        atomicAdd(&g_el[idx], sel);
                        atomicAdd(&g_er[idx], ser);
                    }
                }
            }
        }
    }
    if (fusedW2) {
        __syncthreads();
        if (tid < 3) atomicAdd(&g_wsum[tid], red[tid]);
    }
}

// ---------------- CSR build: per-2048-block scan; boff applied inline downstream --
__global__ void scan1_kernel() {   // grid (10, M_), 2048 nodes/block
    int m = blockIdx.y, b = blockIdx.x, t = threadIdx.x;
    if (m == 0 && b == 0 && t == 0) {               // pre-GEMM2 zero
        g_wsum[0] = 0.f; g_wsum[1] = 0.f; g_wsum[2] = 0.f;
    }
    int i0 = b * 2048 + t * 8;
    int v[8];
    int s = 0;
#pragma unroll
    for (int j = 0; j < 8; j++) {
        int i = i0 + j;
        int d = (i < N_) ? g_deg[m * N_ + i] : 0;
        s += d; v[j] = s;
    }
    __shared__ int sh[256];
    sh[t] = s;
    __syncthreads();
#pragma unroll
    for (int st = 1; st < 256; st <<= 1) {
        int y = (t >= st) ? sh[t - st] : 0;
        __syncthreads();
        sh[t] += y;
        __syncthreads();
    }
    int excl = sh[t] - s;
#pragma unroll
    for (int j = 0; j < 8; j++) {
        int i = i0 + j;
        if (i < N_) g_off[m * (N_ + 1) + i + 1] = excl + v[j];
    }
    if (t == 255) g_bsum[m * 16 + b] = sh[255];
}

// ---------------- scatter (atomic-free; 4 independent edge chains per thread) ----
__global__ __launch_bounds__(256) void scatter_kernel(const int* __restrict__ src,
                                                      const int* __restrict__ dst) {
    __shared__ int sboff[M_ * 16];
    int t = threadIdx.x;
    if (t < M_ * 16) {
        int m = t >> 4, b = t & 15;
        int s = 0;
        for (int k = 0; k < b; k++) s += g_bsum[m * 16 + k];
        sboff[t] = s;
    }
    __syncthreads();

    int t0 = blockIdx.x * 1024;
    int dd[4], rk[4], sr[4], mm[4], off[4];
    bool val[4];
#pragma unroll
    for (int j = 0; j < 4; j++) {
        int i = t0 + t + j * 256;
        val[j] = i < M_ * E_;
        if (val[j]) {
            dd[j] = dst[i];
            rk[j] = g_rank[i];
            sr[j] = src[i];
            mm[j] = i / E_;
        }
    }
#pragma unroll
    for (int j = 0; j < 4; j++)
        if (val[j] && dd[j] != 0)
            off[j] = g_off[mm[j] * (N_ + 1) + dd[j]];
#pragma unroll
    for (int j = 0; j < 4; j++) {
        if (!val[j]) continue;
        int pos;
        if (dd[j] == 0) {
            pos = rk[j];
        } else {
            int blk = (dd[j] - 1) >> 11;
            pos = off[j] + sboff[mm[j] * 16 + blk] + rk[j];
        }
        g_srcs[mm[j] * E_ + pos] = sr[j];
    }
}

// ---------------- GAT aggregate: one warp per (metapath, dst) -------------------
// pass A: exp once per (edge,head) -> 4 head-transposed alpha planes + denominators
// pass B: serial edges, unroll x4, scalar UNNORMALIZED alpha loads; normalize at end
__device__ __forceinline__ void addmul8(float* acc, float a, uint4 u) {
    const __half2* hp = (const __half2*)&u;
#pragma unroll
    for (int j = 0; j < 4; j++) {
        float2 x = __half22float2(hp[j]);
        acc[2 * j]     += a * x.x;
        acc[2 * j + 1] += a * x.y;
    }
}

__global__ __launch_bounds__(256) void agg_kernel(const float* __restrict__ bias) {
    int g = blockIdx.x * blockDim.x + threadIdx.x;
    int warp = g >> 5, lane = g & 31;
    if (warp >= M_ * N_) return;
    int m = warp / N_;
    int n = warp - m * N_;

    int blk = n >> 11;
    int boff = 0;
    for (int b = 0; b < blk; b++) boff += g_bsum[m * 16 + b];
    int end = g_off[m * (N_ + 1) + n + 1] + boff;
    int start;
    if (n == 0)                start = 0;
    else if ((n & 2047) == 0)  start = boff;
    else                       start = g_off[m * (N_ + 1) + n] + boff;

    float4 erd = *(const float4*)&g_er[(size_t)warp * 4];
    const int*    sl  = g_srcs + m * E_;
    const float*  elb = g_el  + (size_t)m * N_ * 4;
    constexpr size_t PLANE = (size_t)M_ * E_;
    float* ea0p = g_ea + 0 * PLANE + (size_t)m * E_;
    float* ea1p = g_ea + 1 * PLANE + (size_t)m * E_;
    float* ea2p = g_ea + 2 * PLANE + (size_t)m * E_;
    float* ea3p = g_ea + 3 * PLANE + (size_t)m * E_;
    const __half* fb  = g_feat + (size_t)m * N_ * HD_;

    // pass A: alphas into transposed planes + denominators
    float s0 = 0, s1 = 0, s2 = 0, s3 = 0;
    for (int i = start + lane; i < end; i += 32) {
        float4 e4 = *(const float4*)&elb[(size_t)sl[i] * 4];
        float p0 = __expf(lrelu(e4.x + erd.x));
        float p1 = __expf(lrelu(e4.y + erd.y));
        float p2 = __expf(lrelu(e4.z + erd.z));
        float p3 = __expf(lrelu(e4.w + erd.w));
        s0 += p0; s1 += p1; s2 += p2; s3 += p3;
        ea0p[i] = p0; ea1p[i] = p1; ea2p[i] = p2; ea3p[i] = p3;
    }
#pragma unroll
    for (int s = 16; s > 0; s >>= 1) {
        s0 += __shfl_xor_sync(0xffffffffu, s0, s);
        s1 += __shfl_xor_sync(0xffffffffu, s1, s);
        s2 += __shfl_xor_sync(0xffffffffu, s2, s);
        s3 += __shfl_xor_sync(0xffffffffu, s3, s);
    }
    int hsel = lane >> 3;           // head for this lane's 8 contiguous cols
    float r_s = hsel == 0 ? 1.f / fmaxf(s0, 1e-9f)
              : hsel == 1 ? 1.f / fmaxf(s1, 1e-9f)
              : hsel == 2 ? 1.f / fmaxf(s2, 1e-9f)
              :             1.f / fmaxf(s3, 1e-9f);
    const float* ab = hsel == 0 ? ea0p : hsel == 1 ? ea1p : hsel == 2 ? ea2p : ea3p;
    int colA = lane << 3;
    const __half* fbc = fb + colA;

    // pass B: unroll x4, 32-bit offsets, unnormalized alphas (normalize once below)
    float acc[8] = {0, 0, 0, 0, 0, 0, 0, 0};
    int i = start;
    for (; i + 4 <= end; i += 4) {
        float a0 = ab[i];
        float a1 = ab[i + 1];
        float a2 = ab[i + 2];
        float a3 = ab[i + 3];
        int sA = sl[i], sB = sl[i + 1], sC = sl[i + 2], sD = sl[i + 3];
        uint4 u0 = *(const uint4*)(fbc + (sA << 8));
        uint4 u1 = *(const uint4*)(fbc + (sB << 8));
        uint4 u2 = *(const uint4*)(fbc + (sC << 8));
        uint4 u3 = *(const uint4*)(fbc + (sD << 8));
        addmul8(acc, a0, u0);
        addmul8(acc, a1, u1);
        addmul8(acc, a2, u2);
        addmul8(acc, a3, u3);
    }
    for (; i < end; i++) {
        float a0 = ab[i];
        uint4 u0 = *(const uint4*)(fbc + (sl[i] << 8));
        addmul8(acc, a0, u0);
    }

    const float* brow = bias + m * HD_ + colA;
    float4 b0 = *(const float4*)brow;
    float4 b1 = *(const float4*)(brow + 4);
    acc[0] = acc[0] * r_s + b0.x; acc[1] = acc[1] * r_s + b0.y;
    acc[2] = acc[2] * r_s + b0.z; acc[3] = acc[3] * r_s + b0.w;
    acc[4] = acc[4] * r_s + b1.x; acc[5] = acc[5] * r_s + b1.y;
    acc[6] = acc[6] * r_s + b1.z; acc[7] = acc[7] * r_s + b1.w;

    __half* zb = g_z + (size_t)warp * HD_ + colA;
    *(uint4*)zb = make_uint4(
        h2u(__floats2half2_rn(acc[0], acc[1])), h2u(__floats2half2_rn(acc[2], acc[3])),
        h2u(__floats2half2_rn(acc[4], acc[5])), h2u(__floats2half2_rn(acc[6], acc[7])));
}

// ---------------- final mix (beta computed inline per block) ----------------
__global__ void final_kernel(float* __restrict__ out) {
    __shared__ float sb[3];
    if (threadIdx.x == 0) {
        float w0 = g_wsum[0] / (float)N_;
        float w1 = g_wsum[1] / (float)N_;
        float w2 = g_wsum[2] / (float)N_;
        float mx = fmaxf(w0, fmaxf(w1, w2));
        float e0 = expf(w0 - mx), e1 = expf(w1 - mx), e2 = expf(w2 - mx);
        float s = e0 + e1 + e2;
        sb[0] = e0 / s; sb[1] = e1 / s; sb[2] = e2 / s;
    }
    __syncthreads();
    int i = blockIdx.x * blockDim.x + threadIdx.x;   // one uint4 = 8 halves
    constexpr int S = N_ * HD_ / 8;
    if (i < M_ * N_) {
        // re-zero el/er/deg for the next replay (last readers: agg / hist)
        float4 z4 = make_float4(0.f, 0.f, 0.f, 0.f);
        *(float4*)&g_el[(size_t)i * 4] = z4;
        *(float4*)&g_er[(size_t)i * 4] = z4;
        g_deg[i] = 0;
    }
    if (i >= S) return;
    float b0 = sb[0], b1 = sb[1], b2 = sb[2];
    const uint4* zp = (const uint4*)g_z;
    uint4 u0 = zp[i], u1 = zp[i + S], u2 = zp[i + 2 * S];
    const __half2* h0 = (const __half2*)&u0;
    const __half2* h1 = (const __half2*)&u1;
    const __half2* h2 = (const __half2*)&u2;
    float r[8];
#pragma unroll
    for (int j = 0; j < 4; j++) {
        float2 x0 = __half22float2(h0[j]);
        float2 x1 = __half22float2(h1[j]);
        float2 x2 = __half22float2(h2[j]);
        r[2 * j]     = b0 * x0.x + b1 * x1.x + b2 * x2.x;
        r[2 * j + 1] = b0 * x0.y + b1 * x1.y + b2 * x2.y;
    }
    float4* op = (float4*)(out + (size_t)i * 8);
    op[0] = make_float4(r[0], r[1], r[2], r[3]);
    op[1] = make_float4(r[4], r[5], r[6], r[7]);
}

// ---------------- launch ----------------
extern "C" void kernel_launch(void* const* d_in, const int* in_sizes, int n_in,
                              void* d_out, int out_size) {
    const float* h      = (const float*)d_in[0];
    const int*   src    = (const int*)d_in[1];
    const int*   dst    = (const int*)d_in[2];
    const float* W      = (const float*)d_in[3];
    const float* attn_l = (const float*)d_in[4];
    const float* attn_r = (const float*)d_in[5];
    const float* bias   = (const float*)d_in[6];
    const float* sem_W1 = (const float*)d_in[7];
    const float* sem_b1 = (const float*)d_in[8];
    const float* sem_W2 = (const float*)d_in[9];
    float* out = (float*)d_out;

    __half *feat, *z, *hh;
    cudaGetSymbolAddress((void**)&feat, g_feat);
    cudaGetSymbolAddress((void**)&z, g_z);
    cudaGetSymbolAddress((void**)&hh, g_hh);

    // h -> fp16 (bit-identical to the in-GEMM quantization)
    convert_h_kernel<<<(N_ * IN_ / 4 + 255) / 256, 256>>>(h);

    // GEMM1 (BN=128, fp16 A, fused el/er + overlapped edge histogram, 16 e/thread)
    constexpr int NBX = (N_ + 127) / 128;       // 157
    constexpr int NBY = HD_ / 128;              // 2
    constexpr int GEMM1_BLOCKS = NBX * NBY * M_;
    constexpr int HIST_BLOCKS  = (M_ * E_ + 4095) / 4096;   // 235
    gemm_tc_kernel<128><<<GEMM1_BLOCKS + HIST_BLOCKS, 256>>>(
        nullptr, hh, W, feat, N_, IN_, HD_,
        0L, (long)IN_ * HD_, (long)N_ * HD_, nullptr, nullptr,
        attn_l, attn_r, dst, NBX, NBY);

    scan1_kernel<<<dim3(10, M_), 256>>>();
    scatter_kernel<<<(M_ * E_ + 1023) / 1024, 256>>>(src, dst);

    agg_kernel<<<(M_ * N_ * 32 + 255) / 256, 256>>>(bias);

    // GEMM2 (BN=128, fp16 A, fused): wsum[m] += sum tanh(z@W1+b1) . W2
    gemm_tc_kernel<128><<<dim3((M_ * N_ + 127) / 128, 1, 1), 256>>>(
        nullptr, z, sem_W1, nullptr, M_ * N_, HD_, HID_,
        0L, 0L, 0L, sem_b1, sem_W2, nullptr, nullptr, nullptr, 0, 0);

    final_kernel<<<(N_ * HD_ / 8 + 255) / 256, 256>>>(out);
}